// round 1
// baseline (speedup 1.0000x reference)
#include <cuda_runtime.h>
#include <cuda_bf16.h>
#include <cstdint>

// Problem constants
#define B_  32
#define S_  512
#define D_  768
#define H_  12
#define HD_ 64
#define SCALE_ 0.125f   // 64^-0.5

#define M_TOT (B_ * S_)          // 16384
#define QKV_N (3 * D_)           // 2304

// Scratch (device globals — allocation-free)
__device__ float g_qkv[(size_t)M_TOT * QKV_N];   // [M, 3D]: per row [q(768) | k(768) | v(768)], head-major inside
__device__ float g_attn[(size_t)M_TOT * D_];     // [M, D] attention output (B,S,H,HD)

// ---------------------------------------------------------------------------
// SGEMM: C[M,N] = A[M,K] @ B[N,K]^T + bias[N]
// BM=BN=128, BK=16, 256 threads, 8x8 per-thread microtile.
// Requires M%128==0, N%128==0, K%16==0 (true for all our shapes).
// ---------------------------------------------------------------------------
#define BM 128
#define BN 128
#define BK 16
#define TM 8
#define TN 8

__global__ __launch_bounds__(256) void gemm_bias_kernel(
    const float* __restrict__ A, const float* __restrict__ Bw,
    const float* __restrict__ bias, float* __restrict__ C,
    int M, int N, int K)
{
    __shared__ float As[BK][BM];
    __shared__ float Bs[BK][BN];

    const int tid = threadIdx.x;
    const int tx  = tid & 15;
    const int ty  = tid >> 4;
    const int m0  = blockIdx.y * BM;
    const int n0  = blockIdx.x * BN;

    float acc[TM][TN];
    #pragma unroll
    for (int i = 0; i < TM; i++)
        #pragma unroll
        for (int j = 0; j < TN; j++) acc[i][j] = 0.0f;

    const float* Ab = A  + (size_t)m0 * K;
    const float* Bb = Bw + (size_t)n0 * K;

    for (int k0 = 0; k0 < K; k0 += BK) {
        #pragma unroll
        for (int r = 0; r < 2; r++) {
            int f   = tid * 2 + r;          // 0..511
            int row = f >> 2;               // 0..127
            int kc  = (f & 3) << 2;         // 0,4,8,12
            float4 a = *(const float4*)(Ab + (size_t)row * K + k0 + kc);
            As[kc + 0][row] = a.x; As[kc + 1][row] = a.y;
            As[kc + 2][row] = a.z; As[kc + 3][row] = a.w;
            float4 b = *(const float4*)(Bb + (size_t)row * K + k0 + kc);
            Bs[kc + 0][row] = b.x; Bs[kc + 1][row] = b.y;
            Bs[kc + 2][row] = b.z; Bs[kc + 3][row] = b.w;
        }
        __syncthreads();

        #pragma unroll
        for (int k = 0; k < BK; k++) {
            float ar[TM], br[TN];
            #pragma unroll
            for (int i = 0; i < TM; i++) ar[i] = As[k][ty * TM + i];
            #pragma unroll
            for (int j = 0; j < TN; j++) br[j] = Bs[k][tx * TN + j];
            #pragma unroll
            for (int i = 0; i < TM; i++)
                #pragma unroll
                for (int j = 0; j < TN; j++)
                    acc[i][j] += ar[i] * br[j];
        }
        __syncthreads();
    }

    // Epilogue: add bias, store (vectorized)
    #pragma unroll
    for (int i = 0; i < TM; i++) {
        int m = m0 + ty * TM + i;
        #pragma unroll
        for (int j4 = 0; j4 < TN; j4 += 4) {
            int n = n0 + tx * TN + j4;
            float4 bsv = *(const float4*)(bias + n);
            float4 o;
            o.x = acc[i][j4 + 0] + bsv.x;
            o.y = acc[i][j4 + 1] + bsv.y;
            o.z = acc[i][j4 + 2] + bsv.z;
            o.w = acc[i][j4 + 3] + bsv.w;
            *(float4*)(C + (size_t)m * N + n) = o;
        }
    }
}

// ---------------------------------------------------------------------------
// Flash attention: per block = (b, h, q-tile of 64 rows).
// 256 threads as 16x16; each thread owns 4 score rows (ty) x 4 cols (tx mapped
// jcol = jj*16+tx) and 4 output cols (dd = tx*4..).
// Online softmax over 8 K/V tiles of 64.
// smem: Qs[64][65] Ks[64][65] Vs[64][64] Ps[64][65]
// ---------------------------------------------------------------------------
#define ATTN_SMEM_FLOATS (64*65 + 64*65 + 64*64 + 64*65)
#define ATTN_SMEM_BYTES  (ATTN_SMEM_FLOATS * 4)

__global__ __launch_bounds__(256) void attn_kernel(
    const float* __restrict__ qkv, float* __restrict__ out)
{
    const int bid = blockIdx.x;            // 0 .. B*H*8-1
    const int qt  = bid & 7;
    const int h   = (bid >> 3) % H_;
    const int b   = bid / (H_ * 8);

    const int tid = threadIdx.x;
    const int tx  = tid & 15;
    const int ty  = tid >> 4;

    extern __shared__ float sm[];
    float* Qs = sm;                  // stride 65
    float* Ks = Qs + 64 * 65;        // stride 65
    float* Vs = Ks + 64 * 65;        // stride 64
    float* Ps = Vs + 64 * 64;        // stride 65

    const float* qbase = qkv + (size_t)(b * S_ + qt * 64) * QKV_N + h * HD_;

    // Load Q tile (scaled)
    for (int t = tid; t < 64 * 16; t += 256) {
        int r  = t >> 4;
        int c4 = (t & 15) << 2;
        float4 v = *(const float4*)(qbase + (size_t)r * QKV_N + c4);
        float* dst = Qs + r * 65 + c4;
        dst[0] = v.x * SCALE_; dst[1] = v.y * SCALE_;
        dst[2] = v.z * SCALE_; dst[3] = v.w * SCALE_;
    }

    float m_i[4], l_i[4], o[4][4];
    #pragma unroll
    for (int i = 0; i < 4; i++) {
        m_i[i] = -1e30f; l_i[i] = 0.0f;
        #pragma unroll
        for (int d = 0; d < 4; d++) o[i][d] = 0.0f;
    }

    for (int kt = 0; kt < 8; kt++) {
        const float* kbase = qkv + (size_t)(b * S_ + kt * 64) * QKV_N + D_ + h * HD_;
        const float* vbase = kbase + D_;

        __syncthreads();   // prev PV done (and Q load on iter 0)
        for (int t = tid; t < 64 * 16; t += 256) {
            int r  = t >> 4;
            int c4 = (t & 15) << 2;
            float4 kk = *(const float4*)(kbase + (size_t)r * QKV_N + c4);
            float* kd = Ks + r * 65 + c4;
            kd[0] = kk.x; kd[1] = kk.y; kd[2] = kk.z; kd[3] = kk.w;
            float4 vv = *(const float4*)(vbase + (size_t)r * QKV_N + c4);
            *(float4*)(Vs + r * 64 + c4) = vv;
        }
        __syncthreads();

        // S = Q K^T  (Q pre-scaled)
        float s[4][4];
        #pragma unroll
        for (int i = 0; i < 4; i++)
            #pragma unroll
            for (int j = 0; j < 4; j++) s[i][j] = 0.0f;

        #pragma unroll 8
        for (int d = 0; d < HD_; d++) {
            float qreg[4], kreg[4];
            #pragma unroll
            for (int ii = 0; ii < 4; ii++) qreg[ii] = Qs[(ty * 4 + ii) * 65 + d];
            #pragma unroll
            for (int jj = 0; jj < 4; jj++) kreg[jj] = Ks[(jj * 16 + tx) * 65 + d];
            #pragma unroll
            for (int ii = 0; ii < 4; ii++)
                #pragma unroll
                for (int jj = 0; jj < 4; jj++)
                    s[ii][jj] += qreg[ii] * kreg[jj];
        }

        // Online softmax update
        #pragma unroll
        for (int ii = 0; ii < 4; ii++) {
            float mx = fmaxf(fmaxf(s[ii][0], s[ii][1]), fmaxf(s[ii][2], s[ii][3]));
            #pragma unroll
            for (int off = 8; off >= 1; off >>= 1)
                mx = fmaxf(mx, __shfl_xor_sync(0xffffffffu, mx, off));
            float mnew = fmaxf(m_i[ii], mx);
            float corr = __expf(m_i[ii] - mnew);
            float rs = 0.0f;
            #pragma unroll
            for (int jj = 0; jj < 4; jj++) {
                float p = __expf(s[ii][jj] - mnew);
                s[ii][jj] = p;
                rs += p;
            }
            #pragma unroll
            for (int off = 8; off >= 1; off >>= 1)
                rs += __shfl_xor_sync(0xffffffffu, rs, off);
            l_i[ii] = l_i[ii] * corr + rs;
            m_i[ii] = mnew;
            #pragma unroll
            for (int d = 0; d < 4; d++) o[ii][d] *= corr;
            #pragma unroll
            for (int jj = 0; jj < 4; jj++)
                Ps[(ty * 4 + ii) * 65 + jj * 16 + tx] = s[ii][jj];
        }
        __syncthreads();

        // O += P @ V
        #pragma unroll 8
        for (int j = 0; j < 64; j++) {
            float4 v4 = *(const float4*)(Vs + j * 64 + tx * 4);
            #pragma unroll
            for (int ii = 0; ii < 4; ii++) {
                float p = Ps[(ty * 4 + ii) * 65 + j];
                o[ii][0] += p * v4.x;
                o[ii][1] += p * v4.y;
                o[ii][2] += p * v4.z;
                o[ii][3] += p * v4.w;
            }
        }
    }

    // Normalize and write out: out[b, q, h*64 + dd]
    float* obase = out + (size_t)(b * S_ + qt * 64) * D_ + h * HD_;
    #pragma unroll
    for (int ii = 0; ii < 4; ii++) {
        float inv = 1.0f / l_i[ii];
        int row = ty * 4 + ii;
        float4 ov;
        ov.x = o[ii][0] * inv; ov.y = o[ii][1] * inv;
        ov.z = o[ii][2] * inv; ov.w = o[ii][3] * inv;
        *(float4*)(obase + (size_t)row * D_ + tx * 4) = ov;
    }
}

// ---------------------------------------------------------------------------
// Launch
// ---------------------------------------------------------------------------
extern "C" void kernel_launch(void* const* d_in, const int* in_sizes, int n_in,
                              void* d_out, int out_size)
{
    const float* x      = (const float*)d_in[0];
    const float* qkv_w  = (const float*)d_in[1];
    const float* qkv_b  = (const float*)d_in[2];
    const float* proj_w = (const float*)d_in[3];
    const float* proj_b = (const float*)d_in[4];
    float* out = (float*)d_out;

    void* qkv_ptr = nullptr;
    void* attn_ptr = nullptr;
    cudaGetSymbolAddress(&qkv_ptr, g_qkv);
    cudaGetSymbolAddress(&attn_ptr, g_attn);
    float* qkv_s  = (float*)qkv_ptr;
    float* attn_s = (float*)attn_ptr;

    cudaFuncSetAttribute(attn_kernel,
                         cudaFuncAttributeMaxDynamicSharedMemorySize,
                         ATTN_SMEM_BYTES);

    // 1) QKV projection: [16384, 768] @ [2304, 768]^T + b -> [16384, 2304]
    gemm_bias_kernel<<<dim3(QKV_N / BN, M_TOT / BM), 256>>>(
        x, qkv_w, qkv_b, qkv_s, M_TOT, QKV_N, D_);

    // 2) Flash attention -> [16384, 768]
    attn_kernel<<<B_ * H_ * (S_ / 64), 256, ATTN_SMEM_BYTES>>>(qkv_s, attn_s);

    // 3) Output projection: [16384, 768] @ [768, 768]^T + b -> d_out
    gemm_bias_kernel<<<dim3(D_ / BN, M_TOT / BM), 256>>>(
        attn_s, proj_w, proj_b, out, M_TOT, D_, D_);
}

// round 2
// speedup vs baseline: 1.8498x; 1.8498x over previous
#include <cuda_runtime.h>
#include <cuda_bf16.h>
#include <cstdint>

// Problem constants
#define B_  32
#define S_  512
#define D_  768
#define H_  12
#define HD_ 64
#define SCALE_ 0.125f   // 64^-0.5

#define M_TOT (B_ * S_)          // 16384
#define QKV_N (3 * D_)           // 2304

// Scratch (device globals — allocation-free)
__device__ float g_qkv[(size_t)M_TOT * QKV_N];   // [M, 3D]
__device__ float g_attn[(size_t)M_TOT * D_];     // [M, D]

// ---------------------------------------------------------------------------
// TF32 tensor-core GEMM: C[M,N] = A[M,K] @ B[N,K]^T + bias[N]
// BM=BN=128, BK=16. 256 threads = 8 warps (2x4), warp tile 64x32.
// mma.sync.aligned.m16n8k8.row.col.f32.tf32.tf32.f32
// Inputs converted to tf32 with cvt.rna (bias-free rounding) at the STS stage.
// ---------------------------------------------------------------------------
#define BM 128
#define BN 128
#define BK 16
#define SKEW 4           // smem stride = BK+SKEW = 20 floats (conflict-free)

__device__ __forceinline__ uint32_t f2tf32(float x) {
    uint32_t r;
    asm("cvt.rna.tf32.f32 %0, %1;" : "=r"(r) : "f"(x));
    return r;
}

__device__ __forceinline__ void mma_tf32(float d[4], const uint32_t a[4],
                                         const uint32_t b[2]) {
    asm volatile(
        "mma.sync.aligned.m16n8k8.row.col.f32.tf32.tf32.f32 "
        "{%0,%1,%2,%3},{%4,%5,%6,%7},{%8,%9},{%0,%1,%2,%3};\n"
        : "+f"(d[0]), "+f"(d[1]), "+f"(d[2]), "+f"(d[3])
        : "r"(a[0]), "r"(a[1]), "r"(a[2]), "r"(a[3]),
          "r"(b[0]), "r"(b[1]));
}

__global__ __launch_bounds__(256, 2) void gemm_tc_kernel(
    const float* __restrict__ A, const float* __restrict__ Bw,
    const float* __restrict__ bias, float* __restrict__ C,
    int M, int N, int K)
{
    __shared__ uint32_t As[BM][BK + SKEW];
    __shared__ uint32_t Bs[BN][BK + SKEW];

    const int tid  = threadIdx.x;
    const int lane = tid & 31;
    const int warp = tid >> 5;
    const int wm   = warp >> 2;        // 0..1
    const int wn   = warp & 3;         // 0..3
    const int m0   = blockIdx.y * BM;
    const int n0   = blockIdx.x * BN;

    // global loader mapping: 512 float4 per tile per matrix; 2 per thread
    // f = i*256 + tid ; row = f>>2 ; kq = (f&3)*4
    const int lrow0 = tid >> 2;              // i=0 row
    const int lrow1 = (256 + tid) >> 2;      // i=1 row (= lrow0 + 64)
    const int lkq   = (tid & 3) << 2;

    const float* Aptr = A  + (size_t)(m0 + lrow0) * K + lkq;
    const float* Bptr = Bw + (size_t)(n0 + lrow0) * K + lkq;

    float acc[4][4][4];   // [mi][ni][reg]
    #pragma unroll
    for (int mi = 0; mi < 4; mi++)
        #pragma unroll
        for (int ni = 0; ni < 4; ni++)
            #pragma unroll
            for (int r = 0; r < 4; r++) acc[mi][ni][r] = 0.0f;

    const int nk = K / BK;
    float4 areg0, areg1, breg0, breg1;

    // preload first tile
    areg0 = *(const float4*)(Aptr);
    areg1 = *(const float4*)(Aptr + (size_t)64 * K);
    breg0 = *(const float4*)(Bptr);
    breg1 = *(const float4*)(Bptr + (size_t)64 * K);

    const int rlo = lane >> 2;     // 0..7
    const int rc  = lane & 3;      // 0..3

    for (int kt = 0; kt < nk; kt++) {
        __syncthreads();
        {
            uint4 pa0 = make_uint4(f2tf32(areg0.x), f2tf32(areg0.y),
                                   f2tf32(areg0.z), f2tf32(areg0.w));
            uint4 pa1 = make_uint4(f2tf32(areg1.x), f2tf32(areg1.y),
                                   f2tf32(areg1.z), f2tf32(areg1.w));
            uint4 pb0 = make_uint4(f2tf32(breg0.x), f2tf32(breg0.y),
                                   f2tf32(breg0.z), f2tf32(breg0.w));
            uint4 pb1 = make_uint4(f2tf32(breg1.x), f2tf32(breg1.y),
                                   f2tf32(breg1.z), f2tf32(breg1.w));
            *(uint4*)&As[lrow0][lkq] = pa0;
            *(uint4*)&As[lrow1][lkq] = pa1;
            *(uint4*)&Bs[lrow0][lkq] = pb0;
            *(uint4*)&Bs[lrow1][lkq] = pb1;
        }
        __syncthreads();

        if (kt + 1 < nk) {
            const float* An = Aptr + (size_t)(kt + 1) * BK;
            const float* Bn = Bptr + (size_t)(kt + 1) * BK;
            areg0 = *(const float4*)(An);
            areg1 = *(const float4*)(An + (size_t)64 * K);
            breg0 = *(const float4*)(Bn);
            breg1 = *(const float4*)(Bn + (size_t)64 * K);
        }

        #pragma unroll
        for (int ks = 0; ks < BK; ks += 8) {
            uint32_t afr[4][4];
            #pragma unroll
            for (int mi = 0; mi < 4; mi++) {
                int rb = wm * 64 + mi * 16 + rlo;
                afr[mi][0] = As[rb][ks + rc];
                afr[mi][1] = As[rb + 8][ks + rc];
                afr[mi][2] = As[rb][ks + rc + 4];
                afr[mi][3] = As[rb + 8][ks + rc + 4];
            }
            uint32_t bfr[4][2];
            #pragma unroll
            for (int ni = 0; ni < 4; ni++) {
                int cb = wn * 32 + ni * 8 + rlo;
                bfr[ni][0] = Bs[cb][ks + rc];
                bfr[ni][1] = Bs[cb][ks + rc + 4];
            }
            #pragma unroll
            for (int mi = 0; mi < 4; mi++)
                #pragma unroll
                for (int ni = 0; ni < 4; ni++)
                    mma_tf32(acc[mi][ni], afr[mi], bfr[ni]);
        }
    }

    // Epilogue: bias + store (float2 per [mi][ni] half-row)
    #pragma unroll
    for (int ni = 0; ni < 4; ni++) {
        int col = n0 + wn * 32 + ni * 8 + rc * 2;
        float2 bv = *(const float2*)(bias + col);
        #pragma unroll
        for (int mi = 0; mi < 4; mi++) {
            int row = m0 + wm * 64 + mi * 16 + rlo;
            float2 o0, o1;
            o0.x = acc[mi][ni][0] + bv.x;
            o0.y = acc[mi][ni][1] + bv.y;
            o1.x = acc[mi][ni][2] + bv.x;
            o1.y = acc[mi][ni][3] + bv.y;
            *(float2*)(C + (size_t)row * N + col)       = o0;
            *(float2*)(C + (size_t)(row + 8) * N + col) = o1;
        }
    }
}

// ---------------------------------------------------------------------------
// Flash attention (unchanged from round 1): per block = (b, h, 64-row q tile)
// ---------------------------------------------------------------------------
#define ATTN_SMEM_FLOATS (64*65 + 64*65 + 64*64 + 64*65)
#define ATTN_SMEM_BYTES  (ATTN_SMEM_FLOATS * 4)

__global__ __launch_bounds__(256) void attn_kernel(
    const float* __restrict__ qkv, float* __restrict__ out)
{
    const int bid = blockIdx.x;
    const int qt  = bid & 7;
    const int h   = (bid >> 3) % H_;
    const int b   = bid / (H_ * 8);

    const int tid = threadIdx.x;
    const int tx  = tid & 15;
    const int ty  = tid >> 4;

    extern __shared__ float sm[];
    float* Qs = sm;
    float* Ks = Qs + 64 * 65;
    float* Vs = Ks + 64 * 65;
    float* Ps = Vs + 64 * 64;

    const float* qbase = qkv + (size_t)(b * S_ + qt * 64) * QKV_N + h * HD_;

    for (int t = tid; t < 64 * 16; t += 256) {
        int r  = t >> 4;
        int c4 = (t & 15) << 2;
        float4 v = *(const float4*)(qbase + (size_t)r * QKV_N + c4);
        float* dst = Qs + r * 65 + c4;
        dst[0] = v.x * SCALE_; dst[1] = v.y * SCALE_;
        dst[2] = v.z * SCALE_; dst[3] = v.w * SCALE_;
    }

    float m_i[4], l_i[4], o[4][4];
    #pragma unroll
    for (int i = 0; i < 4; i++) {
        m_i[i] = -1e30f; l_i[i] = 0.0f;
        #pragma unroll
        for (int d = 0; d < 4; d++) o[i][d] = 0.0f;
    }

    for (int kt = 0; kt < 8; kt++) {
        const float* kbase = qkv + (size_t)(b * S_ + kt * 64) * QKV_N + D_ + h * HD_;
        const float* vbase = kbase + D_;

        __syncthreads();
        for (int t = tid; t < 64 * 16; t += 256) {
            int r  = t >> 4;
            int c4 = (t & 15) << 2;
            float4 kk = *(const float4*)(kbase + (size_t)r * QKV_N + c4);
            float* kd = Ks + r * 65 + c4;
            kd[0] = kk.x; kd[1] = kk.y; kd[2] = kk.z; kd[3] = kk.w;
            float4 vv = *(const float4*)(vbase + (size_t)r * QKV_N + c4);
            *(float4*)(Vs + r * 64 + c4) = vv;
        }
        __syncthreads();

        float s[4][4];
        #pragma unroll
        for (int i = 0; i < 4; i++)
            #pragma unroll
            for (int j = 0; j < 4; j++) s[i][j] = 0.0f;

        #pragma unroll 8
        for (int d = 0; d < HD_; d++) {
            float qreg[4], kreg[4];
            #pragma unroll
            for (int ii = 0; ii < 4; ii++) qreg[ii] = Qs[(ty * 4 + ii) * 65 + d];
            #pragma unroll
            for (int jj = 0; jj < 4; jj++) kreg[jj] = Ks[(jj * 16 + tx) * 65 + d];
            #pragma unroll
            for (int ii = 0; ii < 4; ii++)
                #pragma unroll
                for (int jj = 0; jj < 4; jj++)
                    s[ii][jj] += qreg[ii] * kreg[jj];
        }

        #pragma unroll
        for (int ii = 0; ii < 4; ii++) {
            float mx = fmaxf(fmaxf(s[ii][0], s[ii][1]), fmaxf(s[ii][2], s[ii][3]));
            #pragma unroll
            for (int off = 8; off >= 1; off >>= 1)
                mx = fmaxf(mx, __shfl_xor_sync(0xffffffffu, mx, off));
            float mnew = fmaxf(m_i[ii], mx);
            float corr = __expf(m_i[ii] - mnew);
            float rs = 0.0f;
            #pragma unroll
            for (int jj = 0; jj < 4; jj++) {
                float p = __expf(s[ii][jj] - mnew);
                s[ii][jj] = p;
                rs += p;
            }
            #pragma unroll
            for (int off = 8; off >= 1; off >>= 1)
                rs += __shfl_xor_sync(0xffffffffu, rs, off);
            l_i[ii] = l_i[ii] * corr + rs;
            m_i[ii] = mnew;
            #pragma unroll
            for (int d = 0; d < 4; d++) o[ii][d] *= corr;
            #pragma unroll
            for (int jj = 0; jj < 4; jj++)
                Ps[(ty * 4 + ii) * 65 + jj * 16 + tx] = s[ii][jj];
        }
        __syncthreads();

        #pragma unroll 8
        for (int j = 0; j < 64; j++) {
            float4 v4 = *(const float4*)(Vs + j * 64 + tx * 4);
            #pragma unroll
            for (int ii = 0; ii < 4; ii++) {
                float p = Ps[(ty * 4 + ii) * 65 + j];
                o[ii][0] += p * v4.x;
                o[ii][1] += p * v4.y;
                o[ii][2] += p * v4.z;
                o[ii][3] += p * v4.w;
            }
        }
    }

    float* obase = out + (size_t)(b * S_ + qt * 64) * D_ + h * HD_;
    #pragma unroll
    for (int ii = 0; ii < 4; ii++) {
        float inv = 1.0f / l_i[ii];
        int row = ty * 4 + ii;
        float4 ov;
        ov.x = o[ii][0] * inv; ov.y = o[ii][1] * inv;
        ov.z = o[ii][2] * inv; ov.w = o[ii][3] * inv;
        *(float4*)(obase + (size_t)row * D_ + tx * 4) = ov;
    }
}

// ---------------------------------------------------------------------------
// Launch
// ---------------------------------------------------------------------------
extern "C" void kernel_launch(void* const* d_in, const int* in_sizes, int n_in,
                              void* d_out, int out_size)
{
    const float* x      = (const float*)d_in[0];
    const float* qkv_w  = (const float*)d_in[1];
    const float* qkv_b  = (const float*)d_in[2];
    const float* proj_w = (const float*)d_in[3];
    const float* proj_b = (const float*)d_in[4];
    float* out = (float*)d_out;

    void* qkv_ptr = nullptr;
    void* attn_ptr = nullptr;
    cudaGetSymbolAddress(&qkv_ptr, g_qkv);
    cudaGetSymbolAddress(&attn_ptr, g_attn);
    float* qkv_s  = (float*)qkv_ptr;
    float* attn_s = (float*)attn_ptr;

    cudaFuncSetAttribute(attn_kernel,
                         cudaFuncAttributeMaxDynamicSharedMemorySize,
                         ATTN_SMEM_BYTES);

    // 1) QKV projection: [16384, 768] @ [2304, 768]^T + b
    gemm_tc_kernel<<<dim3(QKV_N / BN, M_TOT / BM), 256>>>(
        x, qkv_w, qkv_b, qkv_s, M_TOT, QKV_N, D_);

    // 2) Flash attention
    attn_kernel<<<B_ * H_ * (S_ / 64), 256, ATTN_SMEM_BYTES>>>(qkv_s, attn_s);

    // 3) Output projection: [16384, 768] @ [768, 768]^T + b
    gemm_tc_kernel<<<dim3(D_ / BN, M_TOT / BM), 256>>>(
        attn_s, proj_w, proj_b, out, M_TOT, D_, D_);
}

// round 3
// speedup vs baseline: 2.8018x; 1.5147x over previous
#include <cuda_runtime.h>
#include <cuda_bf16.h>
#include <cstdint>

// Problem constants
#define B_  32
#define S_  512
#define D_  768
#define H_  12
#define HD_ 64
#define SCALE_ 0.125f   // 64^-0.5
// SCALE * log2(e): scores computed directly in log2 domain
#define QSC 0.18033688011112042f

#define M_TOT (B_ * S_)          // 16384
#define QKV_N (3 * D_)           // 2304

__device__ float g_qkv[(size_t)M_TOT * QKV_N];   // [M, 3D]
__device__ float g_attn[(size_t)M_TOT * D_];     // [M, D]

// ---------------------------------------------------------------------------
// Common helpers
// ---------------------------------------------------------------------------
__device__ __forceinline__ uint32_t f2tf32(float x) {
    uint32_t r;
    asm("cvt.rna.tf32.f32 %0, %1;" : "=r"(r) : "f"(x));
    return r;
}

__device__ __forceinline__ void mma_tf32(float d[4], const uint32_t a[4],
                                         const uint32_t b[2]) {
    asm volatile(
        "mma.sync.aligned.m16n8k8.row.col.f32.tf32.tf32.f32 "
        "{%0,%1,%2,%3},{%4,%5,%6,%7},{%8,%9},{%0,%1,%2,%3};\n"
        : "+f"(d[0]), "+f"(d[1]), "+f"(d[2]), "+f"(d[3])
        : "r"(a[0]), "r"(a[1]), "r"(a[2]), "r"(a[3]),
          "r"(b[0]), "r"(b[1]));
}

// 2^t for t in ~[-60, 0], FMA-pipe only (no MUFU).
__device__ __forceinline__ float exp2_poly(float t) {
    float g  = t + 12582912.0f;            // 1.5 * 2^23 magic
    int   j  = __float_as_int(g);
    float nf = g - 12582912.0f;            // rint(t)
    float f  = t - nf;                     // [-0.5, 0.5]
    float p  = 0.0096181f;
    p = fmaf(p, f, 0.0555041f);
    p = fmaf(p, f, 0.2402265f);
    p = fmaf(p, f, 0.6931472f);
    p = fmaf(p, f, 1.0f);
    int n = j - 0x4B400000;                // rint(t) as int
    return __int_as_float(__float_as_int(p) + (n << 23));
}

// ---------------------------------------------------------------------------
// TF32 tensor-core GEMM, double-buffered smem.
// C[M,N] = A[M,K] @ B[N,K]^T + bias[N]
// BM=BN=128, BK=16, 256 threads = 8 warps (2x4), warp tile 64x32.
// ---------------------------------------------------------------------------
#define BM 128
#define BN 128
#define BK 16
#define SKEW 4

__global__ __launch_bounds__(256, 2) void gemm_tc_kernel(
    const float* __restrict__ A, const float* __restrict__ Bw,
    const float* __restrict__ bias, float* __restrict__ C,
    int M, int N, int K)
{
    __shared__ uint32_t As[2][BM][BK + SKEW];
    __shared__ uint32_t Bs[2][BN][BK + SKEW];

    const int tid  = threadIdx.x;
    const int lane = tid & 31;
    const int warp = tid >> 5;
    const int wm   = warp >> 2;
    const int wn   = warp & 3;
    const int m0   = blockIdx.y * BM;
    const int n0   = blockIdx.x * BN;

    const int lrow0 = tid >> 2;
    const int lrow1 = lrow0 + 64;
    const int lkq   = (tid & 3) << 2;

    const float* Aptr = A  + (size_t)(m0 + lrow0) * K + lkq;
    const float* Bptr = Bw + (size_t)(n0 + lrow0) * K + lkq;

    float acc[4][4][4];
    #pragma unroll
    for (int mi = 0; mi < 4; mi++)
        #pragma unroll
        for (int ni = 0; ni < 4; ni++)
            #pragma unroll
            for (int r = 0; r < 4; r++) acc[mi][ni][r] = 0.0f;

    const int nk = K / BK;
    float4 areg0, areg1, breg0, breg1;

    // tile 0 -> regs -> buf 0
    areg0 = *(const float4*)(Aptr);
    areg1 = *(const float4*)(Aptr + (size_t)64 * K);
    breg0 = *(const float4*)(Bptr);
    breg1 = *(const float4*)(Bptr + (size_t)64 * K);
    *(uint4*)&As[0][lrow0][lkq] = make_uint4(f2tf32(areg0.x), f2tf32(areg0.y),
                                             f2tf32(areg0.z), f2tf32(areg0.w));
    *(uint4*)&As[0][lrow1][lkq] = make_uint4(f2tf32(areg1.x), f2tf32(areg1.y),
                                             f2tf32(areg1.z), f2tf32(areg1.w));
    *(uint4*)&Bs[0][lrow0][lkq] = make_uint4(f2tf32(breg0.x), f2tf32(breg0.y),
                                             f2tf32(breg0.z), f2tf32(breg0.w));
    *(uint4*)&Bs[0][lrow1][lkq] = make_uint4(f2tf32(breg1.x), f2tf32(breg1.y),
                                             f2tf32(breg1.z), f2tf32(breg1.w));
    __syncthreads();

    const int rlo = lane >> 2;
    const int rc  = lane & 3;

    for (int kt = 0; kt < nk; kt++) {
        const int cur = kt & 1;
        const bool more = (kt + 1 < nk);
        if (more) {
            const float* An = Aptr + (size_t)(kt + 1) * BK;
            const float* Bn = Bptr + (size_t)(kt + 1) * BK;
            areg0 = *(const float4*)(An);
            areg1 = *(const float4*)(An + (size_t)64 * K);
            breg0 = *(const float4*)(Bn);
            breg1 = *(const float4*)(Bn + (size_t)64 * K);
        }

        #pragma unroll
        for (int ks = 0; ks < BK; ks += 8) {
            uint32_t afr[4][4];
            #pragma unroll
            for (int mi = 0; mi < 4; mi++) {
                int rb = wm * 64 + mi * 16 + rlo;
                afr[mi][0] = As[cur][rb][ks + rc];
                afr[mi][1] = As[cur][rb + 8][ks + rc];
                afr[mi][2] = As[cur][rb][ks + rc + 4];
                afr[mi][3] = As[cur][rb + 8][ks + rc + 4];
            }
            uint32_t bfr[4][2];
            #pragma unroll
            for (int ni = 0; ni < 4; ni++) {
                int cb = wn * 32 + ni * 8 + rlo;
                bfr[ni][0] = Bs[cur][cb][ks + rc];
                bfr[ni][1] = Bs[cur][cb][ks + rc + 4];
            }
            #pragma unroll
            for (int mi = 0; mi < 4; mi++)
                #pragma unroll
                for (int ni = 0; ni < 4; ni++)
                    mma_tf32(acc[mi][ni], afr[mi], bfr[ni]);
        }

        if (more) {
            const int nxt = cur ^ 1;
            *(uint4*)&As[nxt][lrow0][lkq] = make_uint4(f2tf32(areg0.x), f2tf32(areg0.y),
                                                       f2tf32(areg0.z), f2tf32(areg0.w));
            *(uint4*)&As[nxt][lrow1][lkq] = make_uint4(f2tf32(areg1.x), f2tf32(areg1.y),
                                                       f2tf32(areg1.z), f2tf32(areg1.w));
            *(uint4*)&Bs[nxt][lrow0][lkq] = make_uint4(f2tf32(breg0.x), f2tf32(breg0.y),
                                                       f2tf32(breg0.z), f2tf32(breg0.w));
            *(uint4*)&Bs[nxt][lrow1][lkq] = make_uint4(f2tf32(breg1.x), f2tf32(breg1.y),
                                                       f2tf32(breg1.z), f2tf32(breg1.w));
        }
        __syncthreads();
    }

    #pragma unroll
    for (int ni = 0; ni < 4; ni++) {
        int col = n0 + wn * 32 + ni * 8 + rc * 2;
        float2 bv = *(const float2*)(bias + col);
        #pragma unroll
        for (int mi = 0; mi < 4; mi++) {
            int row = m0 + wm * 64 + mi * 16 + rlo;
            float2 o0, o1;
            o0.x = acc[mi][ni][0] + bv.x;
            o0.y = acc[mi][ni][1] + bv.y;
            o1.x = acc[mi][ni][2] + bv.x;
            o1.y = acc[mi][ni][3] + bv.y;
            *(float2*)(C + (size_t)row * N + col)       = o0;
            *(float2*)(C + (size_t)(row + 8) * N + col) = o1;
        }
    }
}

// ---------------------------------------------------------------------------
// TF32 tensor-core flash attention.
// Block = (b, h, 64-row q tile); 128 threads = 4 warps, warp owns 16 q rows.
// Scores computed in log2 domain (Q pre-scaled by SCALE*log2e).
// smem: Qs[64][68] Ks[64][68] Ps[64][68] (tf32 bits), Vs[64][72] (tf32 bits)
// ---------------------------------------------------------------------------
#define AT_FLOATS (3 * 64 * 68 + 64 * 72)
#define AT_BYTES  (AT_FLOATS * 4)

__global__ __launch_bounds__(128) void attn_tc_kernel(
    const float* __restrict__ qkv, float* __restrict__ out)
{
    const int bid = blockIdx.x;
    const int qt  = bid & 7;
    const int h   = (bid >> 3) % H_;
    const int b   = bid / (H_ * 8);

    const int tid  = threadIdx.x;
    const int lane = tid & 31;
    const int warp = tid >> 5;
    const int qr   = lane >> 2;     // 0..7
    const int qc   = lane & 3;      // 0..3
    const int R    = warp * 16;     // warp's q-row base

    extern __shared__ uint32_t smu[];
    uint32_t* Qs = smu;                 // [64][68]
    uint32_t* Ks = smu + 64 * 68;       // [64][68]
    uint32_t* Ps = smu + 2 * 64 * 68;   // [64][68]
    uint32_t* Vs = smu + 3 * 64 * 68;   // [64][72]

    const float* qbase = qkv + (size_t)(b * S_ + qt * 64) * QKV_N + h * HD_;

    // Load Q (scaled into log2 domain, tf32)
    for (int t = tid; t < 1024; t += 128) {
        int r  = t >> 4;
        int c4 = (t & 15) << 2;
        float4 v = *(const float4*)(qbase + (size_t)r * QKV_N + c4);
        *(uint4*)&Qs[r * 68 + c4] =
            make_uint4(f2tf32(v.x * QSC), f2tf32(v.y * QSC),
                       f2tf32(v.z * QSC), f2tf32(v.w * QSC));
    }

    float m1 = -1e30f, m2 = -1e30f, l1 = 0.0f, l2 = 0.0f;
    float o[8][4];
    #pragma unroll
    for (int nt = 0; nt < 8; nt++)
        #pragma unroll
        for (int r = 0; r < 4; r++) o[nt][r] = 0.0f;

    for (int kt = 0; kt < 8; kt++) {
        const float* kbase = qkv + (size_t)(b * S_ + kt * 64) * QKV_N + D_ + h * HD_;
        const float* vbase = kbase + D_;

        __syncthreads();
        for (int t = tid; t < 1024; t += 128) {
            int r  = t >> 4;
            int c4 = (t & 15) << 2;
            float4 kk = *(const float4*)(kbase + (size_t)r * QKV_N + c4);
            *(uint4*)&Ks[r * 68 + c4] =
                make_uint4(f2tf32(kk.x), f2tf32(kk.y), f2tf32(kk.z), f2tf32(kk.w));
            float4 vv = *(const float4*)(vbase + (size_t)r * QKV_N + c4);
            *(uint4*)&Vs[r * 72 + c4] =
                make_uint4(f2tf32(vv.x), f2tf32(vv.y), f2tf32(vv.z), f2tf32(vv.w));
        }
        __syncthreads();

        // S = Q K^T  (log2 domain)
        float s[8][4];
        #pragma unroll
        for (int nt = 0; nt < 8; nt++)
            #pragma unroll
            for (int r = 0; r < 4; r++) s[nt][r] = 0.0f;

        #pragma unroll
        for (int k8 = 0; k8 < HD_; k8 += 8) {
            uint32_t a[4];
            a[0] = Qs[(R + qr) * 68 + k8 + qc];
            a[1] = Qs[(R + qr + 8) * 68 + k8 + qc];
            a[2] = Qs[(R + qr) * 68 + k8 + qc + 4];
            a[3] = Qs[(R + qr + 8) * 68 + k8 + qc + 4];
            #pragma unroll
            for (int nt = 0; nt < 8; nt++) {
                uint32_t bb[2];
                bb[0] = Ks[(nt * 8 + qr) * 68 + k8 + qc];
                bb[1] = Ks[(nt * 8 + qr) * 68 + k8 + qc + 4];
                mma_tf32(s[nt], a, bb);
            }
        }

        // Online softmax (base-2)
        float mx1 = -1e30f, mx2 = -1e30f;
        #pragma unroll
        for (int nt = 0; nt < 8; nt++) {
            mx1 = fmaxf(mx1, fmaxf(s[nt][0], s[nt][1]));
            mx2 = fmaxf(mx2, fmaxf(s[nt][2], s[nt][3]));
        }
        mx1 = fmaxf(mx1, __shfl_xor_sync(0xffffffffu, mx1, 1));
        mx1 = fmaxf(mx1, __shfl_xor_sync(0xffffffffu, mx1, 2));
        mx2 = fmaxf(mx2, __shfl_xor_sync(0xffffffffu, mx2, 1));
        mx2 = fmaxf(mx2, __shfl_xor_sync(0xffffffffu, mx2, 2));

        float mn1 = fmaxf(m1, mx1);
        float mn2 = fmaxf(m2, mx2);
        float c1 = exp2f(m1 - mn1);
        float c2 = exp2f(m2 - mn2);
        m1 = mn1; m2 = mn2;

        float rs1 = 0.0f, rs2 = 0.0f;
        #pragma unroll
        for (int nt = 0; nt < 8; nt++) {
            s[nt][0] = exp2_poly(s[nt][0] - mn1);
            s[nt][1] = exp2_poly(s[nt][1] - mn1);
            s[nt][2] = exp2_poly(s[nt][2] - mn2);
            s[nt][3] = exp2_poly(s[nt][3] - mn2);
            rs1 += s[nt][0] + s[nt][1];
            rs2 += s[nt][2] + s[nt][3];
        }
        rs1 += __shfl_xor_sync(0xffffffffu, rs1, 1);
        rs1 += __shfl_xor_sync(0xffffffffu, rs1, 2);
        rs2 += __shfl_xor_sync(0xffffffffu, rs2, 1);
        rs2 += __shfl_xor_sync(0xffffffffu, rs2, 2);
        l1 = l1 * c1 + rs1;
        l2 = l2 * c2 + rs2;

        #pragma unroll
        for (int nt = 0; nt < 8; nt++) {
            o[nt][0] *= c1; o[nt][1] *= c1;
            o[nt][2] *= c2; o[nt][3] *= c2;
        }

        // Stage P (tf32) into warp-private Ps rows
        #pragma unroll
        for (int nt = 0; nt < 8; nt++) {
            *(uint2*)&Ps[(R + qr) * 68 + nt * 8 + 2 * qc] =
                make_uint2(f2tf32(s[nt][0]), f2tf32(s[nt][1]));
            *(uint2*)&Ps[(R + qr + 8) * 68 + nt * 8 + 2 * qc] =
                make_uint2(f2tf32(s[nt][2]), f2tf32(s[nt][3]));
        }
        __syncwarp();

        // O += P @ V
        #pragma unroll
        for (int k8 = 0; k8 < 64; k8 += 8) {
            uint32_t a[4];
            a[0] = Ps[(R + qr) * 68 + k8 + qc];
            a[1] = Ps[(R + qr + 8) * 68 + k8 + qc];
            a[2] = Ps[(R + qr) * 68 + k8 + qc + 4];
            a[3] = Ps[(R + qr + 8) * 68 + k8 + qc + 4];
            #pragma unroll
            for (int nt = 0; nt < 8; nt++) {
                uint32_t bb[2];
                bb[0] = Vs[(k8 + qc) * 72 + nt * 8 + qr];
                bb[1] = Vs[(k8 + qc + 4) * 72 + nt * 8 + qr];
                mma_tf32(o[nt], a, bb);
            }
        }
        __syncwarp();
    }

    // Normalize + write: out[b, q, h*64 + col]
    float i1 = 1.0f / l1;
    float i2 = 1.0f / l2;
    float* ob = out + (size_t)(b * S_ + qt * 64) * D_ + h * HD_;
    #pragma unroll
    for (int nt = 0; nt < 8; nt++) {
        int col = nt * 8 + 2 * qc;
        *(float2*)(ob + (size_t)(R + qr) * D_ + col) =
            make_float2(o[nt][0] * i1, o[nt][1] * i1);
        *(float2*)(ob + (size_t)(R + qr + 8) * D_ + col) =
            make_float2(o[nt][2] * i2, o[nt][3] * i2);
    }
}

// ---------------------------------------------------------------------------
// Launch
// ---------------------------------------------------------------------------
extern "C" void kernel_launch(void* const* d_in, const int* in_sizes, int n_in,
                              void* d_out, int out_size)
{
    const float* x      = (const float*)d_in[0];
    const float* qkv_w  = (const float*)d_in[1];
    const float* qkv_b  = (const float*)d_in[2];
    const float* proj_w = (const float*)d_in[3];
    const float* proj_b = (const float*)d_in[4];
    float* out = (float*)d_out;

    void* qkv_ptr = nullptr;
    void* attn_ptr = nullptr;
    cudaGetSymbolAddress(&qkv_ptr, g_qkv);
    cudaGetSymbolAddress(&attn_ptr, g_attn);
    float* qkv_s  = (float*)qkv_ptr;
    float* attn_s = (float*)attn_ptr;

    cudaFuncSetAttribute(attn_tc_kernel,
                         cudaFuncAttributeMaxDynamicSharedMemorySize,
                         AT_BYTES);

    // 1) QKV projection
    gemm_tc_kernel<<<dim3(QKV_N / BN, M_TOT / BM), 256>>>(
        x, qkv_w, qkv_b, qkv_s, M_TOT, QKV_N, D_);

    // 2) Flash attention (tensor cores)
    attn_tc_kernel<<<B_ * H_ * (S_ / 64), 128, AT_BYTES>>>(qkv_s, attn_s);

    // 3) Output projection
    gemm_tc_kernel<<<dim3(D_ / BN, M_TOT / BM), 256>>>(
        attn_s, proj_w, proj_b, out, M_TOT, D_, D_);
}